// round 1
// baseline (speedup 1.0000x reference)
#include <cuda_runtime.h>
#include <math.h>

// Problem constants (fixed shapes for this registry entry)
#define NMAX 32768
#define GMAX 2048
#define FDIM 64
#define WPB  8   // warps per block
#define EPG  4   // edges per warp-group

// Scratch (no cudaMalloc allowed)
__device__ float g_h[NMAX * FDIM];        // node embeddings [N,64]   (8 MB)
__device__ float g_segmax[GMAX * FDIM];   // per-graph per-feature max
__device__ float g_segrcp[GMAX * FDIM];   // per-graph per-feature 1/sum(exp)

// ---------------------------------------------------------------------------
// K1: node MLP  h = (x || u[batch]) -> 64 -> 64 -> 64   (one warp per node)
// ---------------------------------------------------------------------------
__global__ void k_node_mlp(const float* __restrict__ x, const float* __restrict__ u,
                           const int* __restrict__ batch,
                           const float* __restrict__ W1, const float* __restrict__ b1,
                           const float* __restrict__ W2, const float* __restrict__ b2,
                           const float* __restrict__ W3, const float* __restrict__ b3,
                           int n)
{
    __shared__ float sW1[10 * 64], sW2[64 * 64], sW3[64 * 64];
    __shared__ float sb1[64], sb2[64], sb3[64];
    __shared__ float sh[WPB][64];

    for (int i = threadIdx.x; i < 10 * 64; i += blockDim.x) sW1[i] = W1[i];
    for (int i = threadIdx.x; i < 64 * 64; i += blockDim.x) { sW2[i] = W2[i]; sW3[i] = W3[i]; }
    for (int i = threadIdx.x; i < 64; i += blockDim.x) { sb1[i] = b1[i]; sb2[i] = b2[i]; sb3[i] = b3[i]; }
    __syncthreads();

    int wl = threadIdx.x >> 5, lane = threadIdx.x & 31;
    int node = blockIdx.x * WPB + wl;
    if (node >= n) return;

    int bidx = __ldg(batch + node);
    float vin = 0.f;
    if (lane < 6)       vin = x[node * 6 + lane];
    else if (lane < 10) vin = u[bidx * 4 + lane - 6];

    // layer 1 (10 -> 64), relu
    float a0 = sb1[lane], a1 = sb1[lane + 32];
#pragma unroll
    for (int k = 0; k < 10; k++) {
        float xv = __shfl_sync(0xffffffffu, vin, k);
        a0 = fmaf(xv, sW1[k * 64 + lane], a0);
        a1 = fmaf(xv, sW1[k * 64 + lane + 32], a1);
    }
    sh[wl][lane] = fmaxf(a0, 0.f);
    sh[wl][lane + 32] = fmaxf(a1, 0.f);
    __syncwarp();

    // layer 2 (64 -> 64), relu
    a0 = sb2[lane]; a1 = sb2[lane + 32];
#pragma unroll 8
    for (int k = 0; k < 64; k++) {
        float xv = sh[wl][k];
        a0 = fmaf(xv, sW2[k * 64 + lane], a0);
        a1 = fmaf(xv, sW2[k * 64 + lane + 32], a1);
    }
    a0 = fmaxf(a0, 0.f); a1 = fmaxf(a1, 0.f);
    __syncwarp();
    sh[wl][lane] = a0; sh[wl][lane + 32] = a1;
    __syncwarp();

    // layer 3 (64 -> 64), no relu
    a0 = sb3[lane]; a1 = sb3[lane + 32];
#pragma unroll 8
    for (int k = 0; k < 64; k++) {
        float xv = sh[wl][k];
        a0 = fmaf(xv, sW3[k * 64 + lane], a0);
        a1 = fmaf(xv, sW3[k * 64 + lane + 32], a1);
    }
    g_h[node * 64 + lane] = a0;
    g_h[node * 64 + lane + 32] = a1;
}

// ---------------------------------------------------------------------------
// K2: per-graph segment softmax stats (max + 1/sum) — one block per graph.
// batch_hyper is sorted, so each graph's hyperedges are a contiguous run.
// ---------------------------------------------------------------------------
__device__ __forceinline__ int lbound(const int* __restrict__ a, int n, int key)
{
    int lo = 0, hi = n;
    while (lo < hi) { int mid = (lo + hi) >> 1; if (a[mid] < key) lo = mid + 1; else hi = mid; }
    return lo;
}

__global__ void k_segstats(const int* __restrict__ hidx, const int* __restrict__ bh, int E)
{
    int g = blockIdx.x;
    int lo = lbound(bh, E, g);
    int hi = lbound(bh, E, g + 1);

    int f = threadIdx.x & 63;
    int s = threadIdx.x >> 6;   // 0..3 edge slots

    float m = -3.0e38f, sum = 0.f;
    for (int e = lo + s; e < hi; e += 4) {
        int i0 = __ldg(hidx + e), i1 = __ldg(hidx + E + e), i2 = __ldg(hidx + 2 * E + e);
        float xh = g_h[i0 * 64 + f] + g_h[i1 * 64 + f] + g_h[i2 * 64 + f];
        float mn = fmaxf(m, xh);
        sum = sum * __expf(m - mn) + __expf(xh - mn);
        m = mn;
    }
    __shared__ float smx[4][64], ssm[4][64];
    smx[s][f] = m; ssm[s][f] = sum;
    __syncthreads();
    if (threadIdx.x < 64) {
        float M = smx[0][f];
#pragma unroll
        for (int j = 1; j < 4; j++) M = fmaxf(M, smx[j][f]);
        float S = 0.f;
#pragma unroll
        for (int j = 0; j < 4; j++) S += ssm[j][f] * __expf(smx[j][f] - M);
        g_segmax[g * 64 + f] = M;
        g_segrcp[g * 64 + f] = (S > 0.f) ? (1.f / S) : 0.f;
    }
}

// ---------------------------------------------------------------------------
// K3: fused per-edge pipeline. Persistent blocks; weights staged in smem once.
// Each warp owns EPG=4 edges; each lane owns features (lane, lane+32).
// ---------------------------------------------------------------------------
__global__ __launch_bounds__(256, 2)
void k_main(const int* __restrict__ hidx, const int* __restrict__ bh,
            const float* __restrict__ Wt,
            const float* __restrict__ V1, const float* __restrict__ c1,
            const float* __restrict__ V2, const float* __restrict__ c2,
            const float* __restrict__ V3, const float* __restrict__ c3,
            float* __restrict__ out, int E, int writeBatch)
{
    extern __shared__ float smem[];
    float*  sxh  = smem;                          // WPB*EPG*64
    float*  sxhh = sxh  + WPB * EPG * 64;
    float*  so1  = sxhh + WPB * EPG * 64;
    float2* sWp  = (float2*)(so1 + WPB * EPG * 64);   // 64*32  (f2 packs f and f+32)
    float2* sV1p = sWp  + 64 * 32;                    // 128*32
    float2* sV2p = sV1p + 128 * 32;                   // 64*32
    float*  sv   = (float*)(sV2p + 64 * 32);          // V3[64], c1[64], c2[64], c3

    // Stage weights packed as (col f, col f+32)
    for (int i = threadIdx.x; i < 64 * 32; i += 256) {
        int k = i >> 5, j = i & 31;
        sWp[i]  = make_float2(Wt[k * 64 + j],  Wt[k * 64 + j + 32]);
        sV2p[i] = make_float2(V2[k * 64 + j],  V2[k * 64 + j + 32]);
    }
    for (int i = threadIdx.x; i < 128 * 32; i += 256) {
        int k = i >> 5, j = i & 31;
        sV1p[i] = make_float2(V1[k * 64 + j],  V1[k * 64 + j + 32]);
    }
    for (int i = threadIdx.x; i < 64; i += 256) {
        sv[i] = V3[i]; sv[64 + i] = c1[i]; sv[128 + i] = c2[i];
    }
    if (threadIdx.x == 0) sv[192] = c3[0];
    __syncthreads();

    float* sV3 = sv;
    float* sc1 = sv + 64;
    float* sc2 = sv + 128;
    float  c3v = sv[192];

    int lane = threadIdx.x & 31, wl = threadIdx.x >> 5;
    float* mxh  = sxh  + wl * (EPG * 64);
    float* mxhh = sxhh + wl * (EPG * 64);
    float* mo1  = so1  + wl * (EPG * 64);

    int gw = blockIdx.x * WPB + wl;
    int nw = gridDim.x * WPB;
    int ngrp = (E + EPG - 1) / EPG;

    for (int grp = gw; grp < ngrp; grp += nw) {
        __syncwarp();   // protect mxh from previous-iteration readers
        int eb = grp * EPG;
        float cf0[EPG], cf1[EPG];
        int gs0 = 0;

#pragma unroll
        for (int j = 0; j < EPG; j++) {
            int e = eb + j;
            float xa = 0.f, xb = 0.f;
            cf0[j] = 0.f; cf1[j] = 0.f;
            if (e < E) {
                int i0 = __ldg(hidx + e), i1 = __ldg(hidx + E + e), i2 = __ldg(hidx + 2 * E + e);
                int g  = __ldg(bh + e);
                if (j == 0) gs0 = g;
                xa = g_h[i0 * 64 + lane]      + g_h[i1 * 64 + lane]      + g_h[i2 * 64 + lane];
                xb = g_h[i0 * 64 + 32 + lane] + g_h[i1 * 64 + 32 + lane] + g_h[i2 * 64 + 32 + lane];
                cf0[j] = __expf(xa - g_segmax[g * 64 + lane])      * g_segrcp[g * 64 + lane];
                cf1[j] = __expf(xb - g_segmax[g * 64 + 32 + lane]) * g_segrcp[g * 64 + 32 + lane];
            }
            mxh[j * 64 + lane]      = xa;
            mxh[j * 64 + 32 + lane] = xb;
        }
        __syncwarp();

        // GEMV 1: wy = relu(xh @ weight);  xhh = coef * wy
        float a0[EPG], a1[EPG];
#pragma unroll
        for (int j = 0; j < EPG; j++) { a0[j] = 0.f; a1[j] = 0.f; }
#pragma unroll 4
        for (int k4 = 0; k4 < 64; k4 += 4) {
            float4 xv[EPG];
#pragma unroll
            for (int j = 0; j < EPG; j++) xv[j] = *(const float4*)&mxh[j * 64 + k4];
#pragma unroll
            for (int kk = 0; kk < 4; kk++) {
                float2 wv = sWp[(k4 + kk) * 32 + lane];
#pragma unroll
                for (int j = 0; j < EPG; j++) {
                    float xk = ((const float*)&xv[j])[kk];
                    a0[j] = fmaf(xk, wv.x, a0[j]);
                    a1[j] = fmaf(xk, wv.y, a1[j]);
                }
            }
        }
#pragma unroll
        for (int j = 0; j < EPG; j++) {
            mxhh[j * 64 + lane]      = fmaxf(a0[j], 0.f) * cf0[j];
            mxhh[j * 64 + 32 + lane] = fmaxf(a1[j], 0.f) * cf1[j];
        }
        __syncwarp();

        // GEMV 2: o1 = relu([xh | xhh] @ V1 + c1)
#pragma unroll
        for (int j = 0; j < EPG; j++) { a0[j] = sc1[lane]; a1[j] = sc1[lane + 32]; }
#pragma unroll 4
        for (int k4 = 0; k4 < 64; k4 += 4) {
            float4 xv[EPG];
#pragma unroll
            for (int j = 0; j < EPG; j++) xv[j] = *(const float4*)&mxh[j * 64 + k4];
#pragma unroll
            for (int kk = 0; kk < 4; kk++) {
                float2 wv = sV1p[(k4 + kk) * 32 + lane];
#pragma unroll
                for (int j = 0; j < EPG; j++) {
                    float xk = ((const float*)&xv[j])[kk];
                    a0[j] = fmaf(xk, wv.x, a0[j]);
                    a1[j] = fmaf(xk, wv.y, a1[j]);
                }
            }
        }
#pragma unroll 4
        for (int k4 = 0; k4 < 64; k4 += 4) {
            float4 xv[EPG];
#pragma unroll
            for (int j = 0; j < EPG; j++) xv[j] = *(const float4*)&mxhh[j * 64 + k4];
#pragma unroll
            for (int kk = 0; kk < 4; kk++) {
                float2 wv = sV1p[(64 + k4 + kk) * 32 + lane];
#pragma unroll
                for (int j = 0; j < EPG; j++) {
                    float xk = ((const float*)&xv[j])[kk];
                    a0[j] = fmaf(xk, wv.x, a0[j]);
                    a1[j] = fmaf(xk, wv.y, a1[j]);
                }
            }
        }
#pragma unroll
        for (int j = 0; j < EPG; j++) {
            mo1[j * 64 + lane]      = fmaxf(a0[j], 0.f);
            mo1[j * 64 + 32 + lane] = fmaxf(a1[j], 0.f);
        }
        __syncwarp();

        // GEMV 3: o2 = relu(o1 @ V2 + c2), then dot with V3, sigmoid
#pragma unroll
        for (int j = 0; j < EPG; j++) { a0[j] = sc2[lane]; a1[j] = sc2[lane + 32]; }
#pragma unroll 4
        for (int k4 = 0; k4 < 64; k4 += 4) {
            float4 xv[EPG];
#pragma unroll
            for (int j = 0; j < EPG; j++) xv[j] = *(const float4*)&mo1[j * 64 + k4];
#pragma unroll
            for (int kk = 0; kk < 4; kk++) {
                float2 wv = sV2p[(k4 + kk) * 32 + lane];
#pragma unroll
                for (int j = 0; j < EPG; j++) {
                    float xk = ((const float*)&xv[j])[kk];
                    a0[j] = fmaf(xk, wv.x, a0[j]);
                    a1[j] = fmaf(xk, wv.y, a1[j]);
                }
            }
        }
#pragma unroll
        for (int j = 0; j < EPG; j++) {
            float t = fmaxf(a0[j], 0.f) * sV3[lane] + fmaxf(a1[j], 0.f) * sV3[lane + 32];
#pragma unroll
            for (int off = 16; off; off >>= 1) t += __shfl_xor_sync(0xffffffffu, t, off);
            if (lane == 0) {
                int e = eb + j;
                if (e < E) {
                    float z = t + c3v;
                    out[e] = 1.f / (1.f + __expf(-z));
                }
            }
        }
        // second output: batch_hyper as float (consecutive, same graph run → cheap)
        if (writeBatch && lane < EPG) {
            int e = eb + lane;
            if (e < E) out[E + e] = (float)__ldg(bh + e);
        }
        (void)gs0;
    }
}

// ---------------------------------------------------------------------------
// kernel_launch
// Input order: x, u, batch, hyperedge_index, batch_hyper, [r], W1,b1,W2,b2,
//              W3,b3, weight, V1,c1, V2,c2, V3,c3
// ---------------------------------------------------------------------------
extern "C" void kernel_launch(void* const* d_in, const int* in_sizes, int n_in,
                              void* d_out, int out_size)
{
    const float* x     = (const float*)d_in[0];
    const float* u     = (const float*)d_in[1];
    const int*   batch = (const int*)d_in[2];
    const int*   hidx  = (const int*)d_in[3];
    const int*   bh    = (const int*)d_in[4];

    int N = in_sizes[0] / 6;
    int G = in_sizes[1] / 4;
    int E = in_sizes[4];

    int wb = (in_sizes[5] == 1) ? 6 : 5;   // skip scalar "r" if present
    const float* W1 = (const float*)d_in[wb + 0];
    const float* b1 = (const float*)d_in[wb + 1];
    const float* W2 = (const float*)d_in[wb + 2];
    const float* b2 = (const float*)d_in[wb + 3];
    const float* W3 = (const float*)d_in[wb + 4];
    const float* b3 = (const float*)d_in[wb + 5];
    const float* Wt = (const float*)d_in[wb + 6];
    const float* V1 = (const float*)d_in[wb + 7];
    const float* c1 = (const float*)d_in[wb + 8];
    const float* V2 = (const float*)d_in[wb + 9];
    const float* c2 = (const float*)d_in[wb + 10];
    const float* V3 = (const float*)d_in[wb + 11];
    const float* c3 = (const float*)d_in[wb + 12];

    int writeBatch = (out_size >= 2 * E) ? 1 : 0;

    // K1: node MLP
    k_node_mlp<<<(N + WPB - 1) / WPB, 256>>>(x, u, batch, W1, b1, W2, b2, W3, b3, N);

    // K2: segment softmax stats (one block per graph; batch_hyper sorted)
    k_segstats<<<G, 256>>>(hidx, bh, E);

    // K3: fused main kernel (persistent, 2 blocks/SM)
    const int SMEM_MAIN = (3 * WPB * EPG * 64      // activation buffers
                           + 64 * 32 * 2           // weight packed
                           + 128 * 32 * 2          // V1 packed
                           + 64 * 32 * 2           // V2 packed
                           + 193) * (int)sizeof(float);
    cudaFuncSetAttribute(k_main, cudaFuncAttributeMaxDynamicSharedMemorySize, SMEM_MAIN);
    k_main<<<304, 256, SMEM_MAIN>>>(hidx, bh, Wt, V1, c1, V2, c2, V3, c3,
                                    (float*)d_out, E, writeBatch);
}

// round 3
// speedup vs baseline: 2.5218x; 2.5218x over previous
#include <cuda_runtime.h>
#include <cuda_fp16.h>
#include <cstdint>
#include <math.h>

// Problem constants (fixed shapes for this registry entry)
#define NMAX 32768
#define GMAX 2048
#define EMAX 1146880
#define WPB  8

// Scratch (no cudaMalloc allowed)
__device__ float  g_h[NMAX * 64];        // node embeddings [N,64]
__device__ float  g_segmax[GMAX * 64];
__device__ float  g_segrcp[GMAX * 64];
__device__ __half g_xh[(size_t)EMAX * 64];  // hyperedge features, fp16 (147 MB)

// ---------------------------------------------------------------------------
// PTX wrappers (portable tensor path: ldmatrix + mma.sync, compute_103-safe)
// ---------------------------------------------------------------------------
__device__ __forceinline__ uint32_t smem_u32(const void* p) {
    uint32_t a;
    asm("{ .reg .u64 t; cvta.to.shared.u64 t, %1; cvt.u32.u64 %0, t; }" : "=r"(a) : "l"(p));
    return a;
}
__device__ __forceinline__ void ldsm4(uint32_t& r0, uint32_t& r1, uint32_t& r2, uint32_t& r3,
                                      uint32_t addr) {
    asm volatile("ldmatrix.sync.aligned.m8n8.x4.shared.b16 {%0,%1,%2,%3}, [%4];"
                 : "=r"(r0), "=r"(r1), "=r"(r2), "=r"(r3) : "r"(addr));
}
__device__ __forceinline__ void mma_f16(float d[4], uint32_t a0, uint32_t a1, uint32_t a2,
                                        uint32_t a3, uint32_t b0, uint32_t b1) {
    asm volatile(
        "mma.sync.aligned.m16n8k16.row.col.f32.f16.f16.f32 "
        "{%0,%1,%2,%3},{%4,%5,%6,%7},{%8,%9},{%0,%1,%2,%3};"
        : "+f"(d[0]), "+f"(d[1]), "+f"(d[2]), "+f"(d[3])
        : "r"(a0), "r"(a1), "r"(a2), "r"(a3), "r"(b0), "r"(b1));
}

// ---------------------------------------------------------------------------
// K1: node MLP  h = (x || u[batch]) -> 64 -> 64 -> 64   (one warp per node)
// ---------------------------------------------------------------------------
__global__ void k_node_mlp(const float* __restrict__ x, const float* __restrict__ u,
                           const int* __restrict__ batch,
                           const float* __restrict__ W1, const float* __restrict__ b1,
                           const float* __restrict__ W2, const float* __restrict__ b2,
                           const float* __restrict__ W3, const float* __restrict__ b3,
                           int n)
{
    __shared__ float sW1[10 * 64];
    __shared__ float2 sW2p[64 * 32], sW3p[64 * 32];
    __shared__ float sb1[64], sb2[64], sb3[64];
    __shared__ float sh[WPB][64];

    for (int i = threadIdx.x; i < 10 * 64; i += blockDim.x) sW1[i] = W1[i];
    for (int i = threadIdx.x; i < 64 * 32; i += blockDim.x) {
        int k = i >> 5, j = i & 31;
        sW2p[i] = make_float2(W2[k * 64 + j], W2[k * 64 + j + 32]);
        sW3p[i] = make_float2(W3[k * 64 + j], W3[k * 64 + j + 32]);
    }
    for (int i = threadIdx.x; i < 64; i += blockDim.x) { sb1[i] = b1[i]; sb2[i] = b2[i]; sb3[i] = b3[i]; }
    __syncthreads();

    int wl = threadIdx.x >> 5, lane = threadIdx.x & 31;
    int node = blockIdx.x * WPB + wl;
    if (node >= n) return;

    int bidx = __ldg(batch + node);
    float vin = 0.f;
    if (lane < 6)       vin = x[node * 6 + lane];
    else if (lane < 10) vin = u[bidx * 4 + lane - 6];

    float a0 = sb1[lane], a1 = sb1[lane + 32];
#pragma unroll
    for (int k = 0; k < 10; k++) {
        float xv = __shfl_sync(0xffffffffu, vin, k);
        a0 = fmaf(xv, sW1[k * 64 + lane], a0);
        a1 = fmaf(xv, sW1[k * 64 + lane + 32], a1);
    }
    sh[wl][lane] = fmaxf(a0, 0.f);
    sh[wl][lane + 32] = fmaxf(a1, 0.f);
    __syncwarp();

    a0 = sb2[lane]; a1 = sb2[lane + 32];
#pragma unroll 8
    for (int k = 0; k < 64; k++) {
        float xv = sh[wl][k];
        float2 wv = sW2p[k * 32 + lane];
        a0 = fmaf(xv, wv.x, a0);
        a1 = fmaf(xv, wv.y, a1);
    }
    a0 = fmaxf(a0, 0.f); a1 = fmaxf(a1, 0.f);
    __syncwarp();
    sh[wl][lane] = a0; sh[wl][lane + 32] = a1;
    __syncwarp();

    a0 = sb3[lane]; a1 = sb3[lane + 32];
#pragma unroll 8
    for (int k = 0; k < 64; k++) {
        float xv = sh[wl][k];
        float2 wv = sW3p[k * 32 + lane];
        a0 = fmaf(xv, wv.x, a0);
        a1 = fmaf(xv, wv.y, a1);
    }
    g_h[node * 64 + lane] = a0;
    g_h[node * 64 + lane + 32] = a1;
}

// ---------------------------------------------------------------------------
// K2: segment softmax stats + materialize x_hyper as fp16.
// One block per graph; batch_hyper sorted -> contiguous runs.
// ---------------------------------------------------------------------------
__device__ __forceinline__ int lbound(const int* __restrict__ a, int n, int key)
{
    int lo = 0, hi = n;
    while (lo < hi) { int mid = (lo + hi) >> 1; if (a[mid] < key) lo = mid + 1; else hi = mid; }
    return lo;
}

__global__ void k_segstats(const int* __restrict__ hidx, const int* __restrict__ bh, int E)
{
    int g = blockIdx.x;
    int lo = lbound(bh, E, g);
    int hi = lbound(bh, E, g + 1);

    int f = threadIdx.x & 63;
    int s = threadIdx.x >> 6;

    float m = -3.0e38f, sum = 0.f;
    for (int e = lo + s; e < hi; e += 4) {
        int i0 = __ldg(hidx + e), i1 = __ldg(hidx + E + e), i2 = __ldg(hidx + 2 * E + e);
        float xh = g_h[i0 * 64 + f] + g_h[i1 * 64 + f] + g_h[i2 * 64 + f];
        g_xh[(size_t)e * 64 + f] = __float2half(xh);
        float mn = fmaxf(m, xh);
        sum = sum * __expf(m - mn) + __expf(xh - mn);
        m = mn;
    }
    __shared__ float smx[4][64], ssm[4][64];
    smx[s][f] = m; ssm[s][f] = sum;
    __syncthreads();
    if (threadIdx.x < 64) {
        float M = smx[0][f];
#pragma unroll
        for (int j = 1; j < 4; j++) M = fmaxf(M, smx[j][f]);
        float S = 0.f;
#pragma unroll
        for (int j = 0; j < 4; j++) S += ssm[j][f] * __expf(smx[j][f] - M);
        g_segmax[g * 64 + f] = M;
        g_segrcp[g * 64 + f] = (S > 0.f) ? (1.f / S) : 0.f;
    }
}

// ---------------------------------------------------------------------------
// K3: fp16 tensor-core main kernel.
// Persistent 256-thread blocks, 8 warps. Each warp owns a 16-edge tile and
// runs the 3 GEMMs with mma.sync m16n8k16 (f16 in, f32 accum), operands via
// xor-swizzled SMEM + ldmatrix.
//
// SMEM layout (bytes):
//   0      sWt  [64n][64k]  fp16 swz   (8192)
//   8192   sV1  [64n][128k] fp16 swz   (16384)
//   24576  sV2  [64n][64k]  fp16 swz   (8192)
//   32768  c1[64] f32 | 33024 c2[64] | 33280 V3[64] | 33536 c3
//   33792  per-warp: sxh(2048) sxhh(2048) scf(2048)  x 8 warps
// ---------------------------------------------------------------------------
#define OFF_WT  0
#define OFF_V1  8192
#define OFF_V2  24576
#define OFF_C1  32768
#define OFF_C2  33024
#define OFF_V3  33280
#define OFF_C3  33536
#define OFF_WRP 33792
#define WRP_SZ  6144
#define SMEM_MAIN (OFF_WRP + 8 * WRP_SZ)   // 82944

__global__ __launch_bounds__(256, 2)
void k_main_mma(const int* __restrict__ bh,
                const float* __restrict__ Wt,
                const float* __restrict__ V1, const float* __restrict__ c1,
                const float* __restrict__ V2, const float* __restrict__ c2,
                const float* __restrict__ V3, const float* __restrict__ c3,
                float* __restrict__ out, int E, int writeBatch)
{
    extern __shared__ __align__(128) char smem[];
    uint32_t sb = smem_u32(smem);
    int tid = threadIdx.x;

    // ---- stage weights as [n][k] fp16, xor-swizzled per row ----
    for (int i = tid; i < 64 * 64; i += 256) {
        int n = i >> 6, k = i & 63;
        uint32_t off = (uint32_t)n * 128 + (((uint32_t)k * 2) ^ (((uint32_t)n & 7) * 16));
        *(__half*)(smem + OFF_WT + off) = __float2half(Wt[k * 64 + n]);
        *(__half*)(smem + OFF_V2 + off) = __float2half(V2[k * 64 + n]);
    }
    for (int i = tid; i < 64 * 128; i += 256) {
        int n = i >> 7, k = i & 127;
        uint32_t off = (uint32_t)n * 256 + (((uint32_t)k * 2) ^ (((uint32_t)n & 7) * 16));
        *(__half*)(smem + OFF_V1 + off) = __float2half(V1[k * 64 + n]);
    }
    for (int i = tid; i < 64; i += 256) {
        ((float*)(smem + OFF_C1))[i] = c1[i];
        ((float*)(smem + OFF_C2))[i] = c2[i];
        ((float*)(smem + OFF_V3))[i] = V3[i];
    }
    if (tid == 0) *(float*)(smem + OFF_C3) = c3[0];
    __syncthreads();

    const float* sc1 = (const float*)(smem + OFF_C1);
    const float* sc2 = (const float*)(smem + OFF_C2);
    const float* sV3 = (const float*)(smem + OFF_V3);
    const float  c3v = *(const float*)(smem + OFF_C3);

    int warp = tid >> 5, lane = tid & 31;
    char* wbase = smem + OFF_WRP + warp * WRP_SZ;
    char* sxh  = wbase;          // 16 x 128B (also reused for o1)
    char* sxhh = wbase + 2048;
    char* scf  = wbase + 4096;
    uint32_t sxh_u  = sb + OFF_WRP + warp * WRP_SZ;
    uint32_t sxhh_u = sxh_u + 2048;

    // per-lane ldmatrix address components
    int rowA = lane & 15;
    uint32_t aOff = (uint32_t)rowA * 128;
    uint32_t aKx  = ((uint32_t)(lane >> 4)) * 16;           // k-halve select
    uint32_t aXor = ((uint32_t)(rowA & 7)) * 16;

    int rowB = (lane & 7) + ((lane >> 4) & 1) * 8;          // n within 16-tile
    uint32_t bKx  = ((uint32_t)((lane >> 3) & 1)) * 16;     // k-halve select
    uint32_t bXor = ((uint32_t)(lane & 7)) * 16;

    int qr = lane >> 2;       // 0..7 : D-frag row base
    int qc = lane & 3;        // D-frag column pair selector

    int ngrp = (E + 15) >> 4;
    int gwid = blockIdx.x * 8 + warp;
    int nwrp = gridDim.x * 8;

    for (int grp = gwid; grp < ngrp; grp += nwrp) {
        int e0 = grp << 4;
        __syncwarp();

        // ---- load xh (fp16, precomputed), compute softmax coef, fill SMEM ----
        const __half2* xin = (const __half2*)(g_xh + (size_t)e0 * 64);
#pragma unroll 4
        for (int it = 0; it < 16; it++) {
            int e = e0 + it;
            uint32_t off = (uint32_t)it * 128 + (((uint32_t)lane * 4) ^ (((uint32_t)it & 7) * 16));
            if (e < E) {
                int g = __ldg(bh + e);
                __half2 xh2 = xin[it * 32 + lane];
                float2 xv = __half22float2(xh2);
                float2 mv = *(const float2*)(g_segmax + (size_t)g * 64 + 2 * lane);
                float2 rv = *(const float2*)(g_segrcp + (size_t)g * 64 + 2 * lane);
                float cfa = __expf(xv.x - mv.x) * rv.x;
                float cfb = __expf(xv.y - mv.y) * rv.y;
                *(__half2*)(sxh + off) = xh2;
                *(__half2*)(scf + off) = __floats2half2_rn(cfa, cfb);
                if (writeBatch && lane == 0) out[E + e] = (float)g;
            } else {
                *(__half2*)(sxh + off) = __floats2half2_rn(0.f, 0.f);
                *(__half2*)(scf + off) = __floats2half2_rn(0.f, 0.f);
            }
        }
        __syncwarp();

        float d[8][4];

        // ================= GEMM1: D = xh @ weight =================
#pragma unroll
        for (int j = 0; j < 8; j++) { d[j][0] = 0.f; d[j][1] = 0.f; d[j][2] = 0.f; d[j][3] = 0.f; }
#pragma unroll
        for (int kt = 0; kt < 4; kt++) {
            uint32_t a0, a1, a2, a3;
            ldsm4(a0, a1, a2, a3, sxh_u + aOff + (((uint32_t)kt * 32 + aKx) ^ aXor));
#pragma unroll
            for (int jt = 0; jt < 4; jt++) {
                uint32_t b0, b1, b2, b3;
                uint32_t baddr = sb + OFF_WT + (uint32_t)(jt * 16 + rowB) * 128
                               + (((uint32_t)kt * 32 + bKx) ^ bXor);
                ldsm4(b0, b1, b2, b3, baddr);
                mma_f16(d[2 * jt],     a0, a1, a2, a3, b0, b1);
                mma_f16(d[2 * jt + 1], a0, a1, a2, a3, b2, b3);
            }
        }
        // epi1: xhh = cf * relu(D)
#pragma unroll
        for (int j = 0; j < 8; j++) {
            uint32_t cb = (uint32_t)j * 16 + (uint32_t)qc * 4;
            uint32_t o0 = (uint32_t)qr * 128 + (cb ^ ((uint32_t)qr * 16));
            uint32_t o1 = o0 + 1024;   // row qr+8: +8*128; xor term identical
            float2 cfa = __half22float2(*(__half2*)(scf + o0));
            float2 cfb = __half22float2(*(__half2*)(scf + o1));
            *(__half2*)(sxhh + o0) = __floats2half2_rn(fmaxf(d[j][0], 0.f) * cfa.x,
                                                       fmaxf(d[j][1], 0.f) * cfa.y);
            *(__half2*)(sxhh + o1) = __floats2half2_rn(fmaxf(d[j][2], 0.f) * cfb.x,
                                                       fmaxf(d[j][3], 0.f) * cfb.y);
        }
        __syncwarp();

        // ================= GEMM2: D = [xh | xhh] @ V1 =================
#pragma unroll
        for (int j = 0; j < 8; j++) { d[j][0] = 0.f; d[j][1] = 0.f; d[j][2] = 0.f; d[j][3] = 0.f; }
#pragma unroll
        for (int kt = 0; kt < 8; kt++) {
            uint32_t abase = (kt < 4) ? sxh_u : sxhh_u;
            uint32_t a0, a1, a2, a3;
            ldsm4(a0, a1, a2, a3, abase + aOff + (((uint32_t)(kt & 3) * 32 + aKx) ^ aXor));
#pragma unroll
            for (int jt = 0; jt < 4; jt++) {
                uint32_t b0, b1, b2, b3;
                uint32_t baddr = sb + OFF_V1 + (uint32_t)(jt * 16 + rowB) * 256
                               + (((uint32_t)kt * 32 + bKx) ^ bXor);
                ldsm4(b0, b1, b2, b3, baddr);
                mma_f16(d[2 * jt],     a0, a1, a2, a3, b0, b1);
                mma_f16(d[2 * jt + 1], a0, a1, a2, a3, b2, b3);
            }
        }
        // epi2: o1 = relu(D + c1)  -> overwrite sxh
#pragma unroll
        for (int j = 0; j < 8; j++) {
            int col = j * 8 + qc * 2;
            float2 bv = *(const float2*)(sc1 + col);
            uint32_t cb = (uint32_t)j * 16 + (uint32_t)qc * 4;
            uint32_t o0 = (uint32_t)qr * 128 + (cb ^ ((uint32_t)qr * 16));
            uint32_t o1 = o0 + 1024;
            *(__half2*)(sxh + o0) = __floats2half2_rn(fmaxf(d[j][0] + bv.x, 0.f),
                                                      fmaxf(d[j][1] + bv.y, 0.f));
            *(__half2*)(sxh + o1) = __floats2half2_rn(fmaxf(d[j][2] + bv.x, 0.f),
                                                      fmaxf(d[j][3] + bv.y, 0.f));
        }
        __syncwarp();

        // ================= GEMM3: D = o1 @ V2 =================
#pragma unroll
        for (int j = 0; j < 8; j++) { d[j][0] = 0.f; d[j][1] = 0.f; d[j][2] = 0.f; d[j][3] = 0.f; }
#pragma unroll
        for (int kt = 0; kt < 4; kt++) {
            uint32_t a0, a1, a2, a3;
            ldsm4(a0, a1, a2, a3, sxh_u + aOff + (((uint32_t)kt * 32 + aKx) ^ aXor));
#pragma unroll
            for (int jt = 0; jt < 4; jt++) {
                uint32_t b0, b1, b2, b3;
                uint32_t baddr = sb + OFF_V2 + (uint32_t)(jt * 16 + rowB) * 128
                               + (((uint32_t)kt * 32 + bKx) ^ bXor);
                ldsm4(b0, b1, b2, b3, baddr);
                mma_f16(d[2 * jt],     a0, a1, a2, a3, b0, b1);
                mma_f16(d[2 * jt + 1], a0, a1, a2, a3, b2, b3);
            }
        }
        // epi3: o2 = relu(D + c2); z = o2 . V3 + c3; out = sigmoid(z)
        float zlo = 0.f, zhi = 0.f;
#pragma unroll
        for (int j = 0; j < 8; j++) {
            int col = j * 8 + qc * 2;
            float2 bv = *(const float2*)(sc2 + col);
            float2 wv = *(const float2*)(sV3 + col);
            zlo = fmaf(fmaxf(d[j][0] + bv.x, 0.f), wv.x, zlo);
            zlo = fmaf(fmaxf(d[j][1] + bv.y, 0.f), wv.y, zlo);
            zhi = fmaf(fmaxf(d[j][2] + bv.x, 0.f), wv.x, zhi);
            zhi = fmaf(fmaxf(d[j][3] + bv.y, 0.f), wv.y, zhi);
        }
        zlo += __shfl_xor_sync(0xffffffffu, zlo, 1);
        zlo += __shfl_xor_sync(0xffffffffu, zlo, 2);
        zhi += __shfl_xor_sync(0xffffffffu, zhi, 1);
        zhi += __shfl_xor_sync(0xffffffffu, zhi, 2);
        if (qc == 0) {
            int ea = e0 + qr, eb = e0 + qr + 8;
            if (ea < E) out[ea] = 1.f / (1.f + __expf(-(zlo + c3v)));
            if (eb < E) out[eb] = 1.f / (1.f + __expf(-(zhi + c3v)));
        }
    }
}

// ---------------------------------------------------------------------------
// kernel_launch
// ---------------------------------------------------------------------------
extern "C" void kernel_launch(void* const* d_in, const int* in_sizes, int n_in,
                              void* d_out, int out_size)
{
    const float* x     = (const float*)d_in[0];
    const float* u     = (const float*)d_in[1];
    const int*   batch = (const int*)d_in[2];
    const int*   hidx  = (const int*)d_in[3];
    const int*   bh    = (const int*)d_in[4];

    int N = in_sizes[0] / 6;
    int G = in_sizes[1] / 4;
    int E = in_sizes[4];

    int wb = (in_sizes[5] == 1) ? 6 : 5;   // skip scalar "r" if present
    const float* W1 = (const float*)d_in[wb + 0];
    const float* b1 = (const float*)d_in[wb + 1];
    const float* W2 = (const float*)d_in[wb + 2];
    const float* b2 = (const float*)d_in[wb + 3];
    const float* W3 = (const float*)d_in[wb + 4];
    const float* b3 = (const float*)d_in[wb + 5];
    const float* Wt = (const float*)d_in[wb + 6];
    const float* V1 = (const float*)d_in[wb + 7];
    const float* c1 = (const float*)d_in[wb + 8];
    const float* V2 = (const float*)d_in[wb + 9];
    const float* c2 = (const float*)d_in[wb + 10];
    const float* V3 = (const float*)d_in[wb + 11];
    const float* c3 = (const float*)d_in[wb + 12];

    int writeBatch = (out_size >= 2 * E) ? 1 : 0;

    k_node_mlp<<<(N + WPB - 1) / WPB, 256>>>(x, u, batch, W1, b1, W2, b2, W3, b3, N);
    k_segstats<<<G, 256>>>(hidx, bh, E);

    int nsm = 148;
    cudaDeviceGetAttribute(&nsm, cudaDevAttrMultiProcessorCount, 0);
    cudaFuncSetAttribute(k_main_mma, cudaFuncAttributeMaxDynamicSharedMemorySize, SMEM_MAIN);
    k_main_mma<<<nsm * 2, 256, SMEM_MAIN>>>(bh, Wt, V1, c1, V2, c2, V3, c3,
                                            (float*)d_out, E, writeBatch);
}

// round 4
// speedup vs baseline: 2.5418x; 1.0079x over previous
#include <cuda_runtime.h>
#include <cuda_fp16.h>
#include <cstdint>
#include <math.h>

// Problem constants (fixed shapes for this registry entry)
#define NMAX 32768
#define GMAX 2048
#define EMAX 1146880
#define WPB  8

// Scratch (no cudaMalloc allowed)
__device__ float  g_h[NMAX * 64];        // node embeddings [N,64]
__device__ float  g_segmax[GMAX * 64];
__device__ float  g_segrcp[GMAX * 64];
__device__ __half g_xh[(size_t)EMAX * 64];  // hyperedge features, fp16 (147 MB)

// ---------------------------------------------------------------------------
// PTX wrappers (portable tensor path: ldmatrix + mma.sync, compute_103-safe)
// ---------------------------------------------------------------------------
__device__ __forceinline__ uint32_t smem_u32(const void* p) {
    uint32_t a;
    asm("{ .reg .u64 t; cvta.to.shared.u64 t, %1; cvt.u32.u64 %0, t; }" : "=r"(a) : "l"(p));
    return a;
}
__device__ __forceinline__ void ldsm4(uint32_t& r0, uint32_t& r1, uint32_t& r2, uint32_t& r3,
                                      uint32_t addr) {
    asm volatile("ldmatrix.sync.aligned.m8n8.x4.shared.b16 {%0,%1,%2,%3}, [%4];"
                 : "=r"(r0), "=r"(r1), "=r"(r2), "=r"(r3) : "r"(addr));
}
__device__ __forceinline__ void mma_f16(float d[4], uint32_t a0, uint32_t a1, uint32_t a2,
                                        uint32_t a3, uint32_t b0, uint32_t b1) {
    asm volatile(
        "mma.sync.aligned.m16n8k16.row.col.f32.f16.f16.f32 "
        "{%0,%1,%2,%3},{%4,%5,%6,%7},{%8,%9},{%0,%1,%2,%3};"
        : "+f"(d[0]), "+f"(d[1]), "+f"(d[2]), "+f"(d[3])
        : "r"(a0), "r"(a1), "r"(a2), "r"(a3), "r"(b0), "r"(b1));
}
// pack two f32 into half2 register (lo, hi)
__device__ __forceinline__ uint32_t pack_h2(float lo, float hi) {
    uint32_t r;
    asm("cvt.rn.f16x2.f32 %0, %1, %2;" : "=r"(r) : "f"(hi), "f"(lo));
    return r;
}

// ---------------------------------------------------------------------------
// K1: node MLP  h = (x || u[batch]) -> 64 -> 64 -> 64   (one warp per node)
// ---------------------------------------------------------------------------
__global__ void k_node_mlp(const float* __restrict__ x, const float* __restrict__ u,
                           const int* __restrict__ batch,
                           const float* __restrict__ W1, const float* __restrict__ b1,
                           const float* __restrict__ W2, const float* __restrict__ b2,
                           const float* __restrict__ W3, const float* __restrict__ b3,
                           int n)
{
    __shared__ float sW1[10 * 64];
    __shared__ float2 sW2p[64 * 32], sW3p[64 * 32];
    __shared__ float sb1[64], sb2[64], sb3[64];
    __shared__ float sh[WPB][64];

    for (int i = threadIdx.x; i < 10 * 64; i += blockDim.x) sW1[i] = W1[i];
    for (int i = threadIdx.x; i < 64 * 32; i += blockDim.x) {
        int k = i >> 5, j = i & 31;
        sW2p[i] = make_float2(W2[k * 64 + j], W2[k * 64 + j + 32]);
        sW3p[i] = make_float2(W3[k * 64 + j], W3[k * 64 + j + 32]);
    }
    for (int i = threadIdx.x; i < 64; i += blockDim.x) { sb1[i] = b1[i]; sb2[i] = b2[i]; sb3[i] = b3[i]; }
    __syncthreads();

    int wl = threadIdx.x >> 5, lane = threadIdx.x & 31;
    int node = blockIdx.x * WPB + wl;
    if (node >= n) return;

    int bidx = __ldg(batch + node);
    float vin = 0.f;
    if (lane < 6)       vin = x[node * 6 + lane];
    else if (lane < 10) vin = u[bidx * 4 + lane - 6];

    float a0 = sb1[lane], a1 = sb1[lane + 32];
#pragma unroll
    for (int k = 0; k < 10; k++) {
        float xv = __shfl_sync(0xffffffffu, vin, k);
        a0 = fmaf(xv, sW1[k * 64 + lane], a0);
        a1 = fmaf(xv, sW1[k * 64 + lane + 32], a1);
    }
    sh[wl][lane] = fmaxf(a0, 0.f);
    sh[wl][lane + 32] = fmaxf(a1, 0.f);
    __syncwarp();

    a0 = sb2[lane]; a1 = sb2[lane + 32];
#pragma unroll 8
    for (int k = 0; k < 64; k++) {
        float xv = sh[wl][k];
        float2 wv = sW2p[k * 32 + lane];
        a0 = fmaf(xv, wv.x, a0);
        a1 = fmaf(xv, wv.y, a1);
    }
    a0 = fmaxf(a0, 0.f); a1 = fmaxf(a1, 0.f);
    __syncwarp();
    sh[wl][lane] = a0; sh[wl][lane + 32] = a1;
    __syncwarp();

    a0 = sb3[lane]; a1 = sb3[lane + 32];
#pragma unroll 8
    for (int k = 0; k < 64; k++) {
        float xv = sh[wl][k];
        float2 wv = sW3p[k * 32 + lane];
        a0 = fmaf(xv, wv.x, a0);
        a1 = fmaf(xv, wv.y, a1);
    }
    g_h[node * 64 + lane] = a0;
    g_h[node * 64 + lane + 32] = a1;
}

// ---------------------------------------------------------------------------
// K2: segment softmax stats + materialize x_hyper as fp16.
// One block per graph (512 threads, 8 edge slots); batch_hyper sorted.
// ---------------------------------------------------------------------------
__device__ __forceinline__ int lbound(const int* __restrict__ a, int n, int key)
{
    int lo = 0, hi = n;
    while (lo < hi) { int mid = (lo + hi) >> 1; if (a[mid] < key) lo = mid + 1; else hi = mid; }
    return lo;
}

__global__ __launch_bounds__(512)
void k_segstats(const int* __restrict__ hidx, const int* __restrict__ bh, int E)
{
    int g = blockIdx.x;
    int lo = lbound(bh, E, g);
    int hi = lbound(bh, E, g + 1);

    int f = threadIdx.x & 63;
    int s = threadIdx.x >> 6;   // 0..7 edge slots

    float m = -3.0e38f, sum = 0.f;
    for (int e = lo + s; e < hi; e += 8) {
        int i0 = __ldg(hidx + e), i1 = __ldg(hidx + E + e), i2 = __ldg(hidx + 2 * E + e);
        float xh = g_h[i0 * 64 + f] + g_h[i1 * 64 + f] + g_h[i2 * 64 + f];
        g_xh[(size_t)e * 64 + f] = __float2half(xh);
        float mn = fmaxf(m, xh);
        sum = sum * __expf(m - mn) + __expf(xh - mn);
        m = mn;
    }
    __shared__ float smx[8][64], ssm[8][64];
    smx[s][f] = m; ssm[s][f] = sum;
    __syncthreads();
    if (threadIdx.x < 64) {
        float M = smx[0][f];
#pragma unroll
        for (int j = 1; j < 8; j++) M = fmaxf(M, smx[j][f]);
        float S = 0.f;
#pragma unroll
        for (int j = 0; j < 8; j++) S += ssm[j][f] * __expf(smx[j][f] - M);
        g_segmax[g * 64 + f] = M;
        g_segrcp[g * 64 + f] = (S > 0.f) ? (1.f / S) : 0.f;
    }
}

// ---------------------------------------------------------------------------
// K3: fp16 tensor-core main kernel with in-register GEMM chaining.
// Each warp owns a 16-edge tile. D-fragments of GEMM1/GEMM2 are converted
// in registers into A-fragments of GEMM2/GEMM3 (layout identity of
// m16n8k16 D-frag pairs with m16k16 A-frags) — no intermediate SMEM.
//
// SMEM layout (bytes):
//   0      sWt  [64n][64k]  fp16 swz   (8192)
//   8192   sV1  [64n][128k] fp16 swz   (16384)
//   24576  sV2  [64n][64k]  fp16 swz   (8192)
//   32768  c1[64] f32 | 33024 c2[64] | 33280 V3[64] | 33536 c3
//   33792  per-warp: sxh(2048) scf(2048)  x 8 warps
// ---------------------------------------------------------------------------
#define OFF_WT  0
#define OFF_V1  8192
#define OFF_V2  24576
#define OFF_C1  32768
#define OFF_C2  33024
#define OFF_V3  33280
#define OFF_C3  33536
#define OFF_WRP 33792
#define WRP_SZ  4096
#define SMEM_MAIN (OFF_WRP + 8 * WRP_SZ)   // 66560

__global__ __launch_bounds__(256, 2)
void k_main_mma(const int* __restrict__ bh,
                const float* __restrict__ Wt,
                const float* __restrict__ V1, const float* __restrict__ c1,
                const float* __restrict__ V2, const float* __restrict__ c2,
                const float* __restrict__ V3, const float* __restrict__ c3,
                float* __restrict__ out, int E, int writeBatch)
{
    extern __shared__ __align__(128) char smem[];
    uint32_t sb = smem_u32(smem);
    int tid = threadIdx.x;

    // ---- stage weights as [n][k] fp16, xor-swizzled per row ----
    for (int i = tid; i < 64 * 64; i += 256) {
        int n = i >> 6, k = i & 63;
        uint32_t off = (uint32_t)n * 128 + (((uint32_t)k * 2) ^ (((uint32_t)n & 7) * 16));
        *(__half*)(smem + OFF_WT + off) = __float2half(Wt[k * 64 + n]);
        *(__half*)(smem + OFF_V2 + off) = __float2half(V2[k * 64 + n]);
    }
    for (int i = tid; i < 64 * 128; i += 256) {
        int n = i >> 7, k = i & 127;
        uint32_t off = (uint32_t)n * 256 + (((uint32_t)k * 2) ^ (((uint32_t)n & 7) * 16));
        *(__half*)(smem + OFF_V1 + off) = __float2half(V1[k * 64 + n]);
    }
    for (int i = tid; i < 64; i += 256) {
        ((float*)(smem + OFF_C1))[i] = c1[i];
        ((float*)(smem + OFF_C2))[i] = c2[i];
        ((float*)(smem + OFF_V3))[i] = V3[i];
    }
    if (tid == 0) *(float*)(smem + OFF_C3) = c3[0];
    __syncthreads();

    const float* sc1 = (const float*)(smem + OFF_C1);
    const float* sc2 = (const float*)(smem + OFF_C2);
    const float* sV3 = (const float*)(smem + OFF_V3);
    const float  c3v = *(const float*)(smem + OFF_C3);

    int warp = tid >> 5, lane = tid & 31;
    char* wbase = smem + OFF_WRP + warp * WRP_SZ;
    char* sxh  = wbase;          // 16 x 128B
    char* scf  = wbase + 2048;
    uint32_t sxh_u = sb + OFF_WRP + warp * WRP_SZ;

    // per-lane ldmatrix address components
    int rowA = lane & 15;
    uint32_t aOff = (uint32_t)rowA * 128;
    uint32_t aKx  = ((uint32_t)(lane >> 4)) * 16;           // k-halve select
    uint32_t aXor = ((uint32_t)(rowA & 7)) * 16;

    int rowB = (lane & 7) + ((lane >> 4) & 1) * 8;          // n within 16-tile
    uint32_t bKx  = ((uint32_t)((lane >> 3) & 1)) * 16;     // k-halve select
    uint32_t bXor = ((uint32_t)(lane & 7)) * 16;

    int qr = lane >> 2;       // 0..7 : D-frag row base
    int qc = lane & 3;        // D-frag column pair selector
    uint32_t qxor = (uint32_t)qr * 16;

    int ngrp = (E + 15) >> 4;
    int gwid = blockIdx.x * 8 + warp;
    int nwrp = gridDim.x * 8;

    for (int grp = gwid; grp < ngrp; grp += nwrp) {
        int e0 = grp << 4;
        __syncwarp();

        // ---- stage: load xh (fp16), compute softmax coef, fill sxh/scf ----
        const __half2* xin = (const __half2*)(g_xh + (size_t)e0 * 64);
#pragma unroll 4
        for (int it = 0; it < 16; it++) {
            int e = e0 + it;
            uint32_t off = (uint32_t)it * 128 + (((uint32_t)lane * 4) ^ (((uint32_t)it & 7) * 16));
            if (e < E) {
                int g = __ldg(bh + e);
                __half2 xh2 = xin[it * 32 + lane];
                float2 xv = __half22float2(xh2);
                float2 mv = *(const float2*)(g_segmax + (size_t)g * 64 + 2 * lane);
                float2 rv = *(const float2*)(g_segrcp + (size_t)g * 64 + 2 * lane);
                float cfa = __expf(xv.x - mv.x) * rv.x;
                float cfb = __expf(xv.y - mv.y) * rv.y;
                *(__half2*)(sxh + off) = xh2;
                *(__half2*)(scf + off) = __floats2half2_rn(cfa, cfb);
                if (writeBatch && lane == 0) out[E + e] = (float)g;
            } else {
                *(__half2*)(sxh + off) = __floats2half2_rn(0.f, 0.f);
                *(__half2*)(scf + off) = __floats2half2_rn(0.f, 0.f);
            }
        }
        __syncwarp();

        float d[8][4];
        uint32_t axh[4][4];    // A-frags of xh (k 0..63), reused by GEMM1+GEMM2
        uint32_t ax2[4][4];    // A-frags of xhh (GEMM2 k 64..127), then o1 (GEMM3)

        // ================= GEMM1: D = xh @ weight =================
#pragma unroll
        for (int j = 0; j < 8; j++) { d[j][0] = 0.f; d[j][1] = 0.f; d[j][2] = 0.f; d[j][3] = 0.f; }
#pragma unroll
        for (int kt = 0; kt < 4; kt++) {
            ldsm4(axh[kt][0], axh[kt][1], axh[kt][2], axh[kt][3],
                  sxh_u + aOff + (((uint32_t)kt * 32 + aKx) ^ aXor));
#pragma unroll
            for (int jt = 0; jt < 4; jt++) {
                uint32_t b0, b1, b2, b3;
                uint32_t baddr = sb + OFF_WT + (uint32_t)(jt * 16 + rowB) * 128
                               + (((uint32_t)kt * 32 + bKx) ^ bXor);
                ldsm4(b0, b1, b2, b3, baddr);
                mma_f16(d[2 * jt],     axh[kt][0], axh[kt][1], axh[kt][2], axh[kt][3], b0, b1);
                mma_f16(d[2 * jt + 1], axh[kt][0], axh[kt][1], axh[kt][2], axh[kt][3], b2, b3);
            }
        }
        // epi1 (in registers): xhh = cf * relu(D) -> A-frags for GEMM2 k 64..127
#pragma unroll
        for (int kt = 0; kt < 4; kt++) {
            int j0 = 2 * kt, j1 = j0 + 1;
            uint32_t o00 = (uint32_t)qr * 128 + (((uint32_t)(j0 * 16 + qc * 4)) ^ qxor);
            uint32_t o10 = (uint32_t)qr * 128 + (((uint32_t)(j1 * 16 + qc * 4)) ^ qxor);
            float2 cfa = __half22float2(*(__half2*)(scf + o00));
            float2 cfb = __half22float2(*(__half2*)(scf + o00 + 1024));
            float2 cfc = __half22float2(*(__half2*)(scf + o10));
            float2 cfd = __half22float2(*(__half2*)(scf + o10 + 1024));
            ax2[kt][0] = pack_h2(fmaxf(d[j0][0], 0.f) * cfa.x, fmaxf(d[j0][1], 0.f) * cfa.y);
            ax2[kt][1] = pack_h2(fmaxf(d[j0][2], 0.f) * cfb.x, fmaxf(d[j0][3], 0.f) * cfb.y);
            ax2[kt][2] = pack_h2(fmaxf(d[j1][0], 0.f) * cfc.x, fmaxf(d[j1][1], 0.f) * cfc.y);
            ax2[kt][3] = pack_h2(fmaxf(d[j1][2], 0.f) * cfd.x, fmaxf(d[j1][3], 0.f) * cfd.y);
        }

        // ================= GEMM2: D = [xh | xhh] @ V1 =================
#pragma unroll
        for (int j = 0; j < 8; j++) { d[j][0] = 0.f; d[j][1] = 0.f; d[j][2] = 0.f; d[j][3] = 0.f; }
#pragma unroll
        for (int kt = 0; kt < 8; kt++) {
            const uint32_t* a = (kt < 4) ? axh[kt] : ax2[kt - 4];
#pragma unroll
            for (int jt = 0; jt < 4; jt++) {
                uint32_t b0, b1, b2, b3;
                uint32_t baddr = sb + OFF_V1 + (uint32_t)(jt * 16 + rowB) * 256
                               + (((uint32_t)kt * 32 + bKx) ^ bXor);
                ldsm4(b0, b1, b2, b3, baddr);
                mma_f16(d[2 * jt],     a[0], a[1], a[2], a[3], b0, b1);
                mma_f16(d[2 * jt + 1], a[0], a[1], a[2], a[3], b2, b3);
            }
        }
        // epi2 (in registers): o1 = relu(D + c1) -> A-frags for GEMM3
#pragma unroll
        for (int kt = 0; kt < 4; kt++) {
            int j0 = 2 * kt, j1 = j0 + 1;
            float2 bv0 = *(const float2*)(sc1 + j0 * 8 + qc * 2);
            float2 bv1 = *(const float2*)(sc1 + j1 * 8 + qc * 2);
            ax2[kt][0] = pack_h2(fmaxf(d[j0][0] + bv0.x, 0.f), fmaxf(d[j0][1] + bv0.y, 0.f));
            ax2[kt][1] = pack_h2(fmaxf(d[j0][2] + bv0.x, 0.f), fmaxf(d[j0][3] + bv0.y, 0.f));
            ax2[kt][2] = pack_h2(fmaxf(d[j1][0] + bv1.x, 0.f), fmaxf(d[j1][1] + bv1.y, 0.f));
            ax2[kt][3] = pack_h2(fmaxf(d[j1][2] + bv1.x, 0.f), fmaxf(d[j1][3] + bv1.y, 0.f));
        }

        // ================= GEMM3: D = o1 @ V2 =================
#pragma unroll
        for (int j = 0; j < 8; j++) { d[j][0] = 0.f; d[j][1] = 0.f; d[j][2] = 0.f; d[j][3] = 0.f; }
#pragma unroll
        for (int kt = 0; kt < 4; kt++) {
#pragma unroll
            for (int jt = 0; jt < 4; jt++) {
                uint32_t b0, b1, b2, b3;
                uint32_t baddr = sb + OFF_V2 + (uint32_t)(jt * 16 + rowB) * 128
                               + (((uint32_t)kt * 32 + bKx) ^ bXor);
                ldsm4(b0, b1, b2, b3, baddr);
                mma_f16(d[2 * jt],     ax2[kt][0], ax2[kt][1], ax2[kt][2], ax2[kt][3], b0, b1);
                mma_f16(d[2 * jt + 1], ax2[kt][0], ax2[kt][1], ax2[kt][2], ax2[kt][3], b2, b3);
            }
        }
        // epi3: o2 = relu(D + c2); z = o2 . V3 + c3; out = sigmoid(z)
        float zlo = 0.f, zhi = 0.f;
#pragma unroll
        for (int j = 0; j < 8; j++) {
            int col = j * 8 + qc * 2;
            float2 bv = *(const float2*)(sc2 + col);
            float2 wv = *(const float2*)(sV3 + col);
            zlo = fmaf(fmaxf(d[j][0] + bv.x, 0.f), wv.x, zlo);
            zlo = fmaf(fmaxf(d[j][1] + bv.y, 0.f), wv.y, zlo);
            zhi = fmaf(fmaxf(d[j][2] + bv.x, 0.f), wv.x, zhi);
            zhi = fmaf(fmaxf(d[j][3] + bv.y, 0.f), wv.y, zhi);
        }
        zlo += __shfl_xor_sync(0xffffffffu, zlo, 1);
        zlo += __shfl_xor_sync(0xffffffffu, zlo, 2);
        zhi += __shfl_xor_sync(0xffffffffu, zhi, 1);
        zhi += __shfl_xor_sync(0xffffffffu, zhi, 2);
        if (qc == 0) {
            int ea = e0 + qr, eb = e0 + qr + 8;
            if (ea < E) out[ea] = 1.f / (1.f + __expf(-(zlo + c3v)));
            if (eb < E) out[eb] = 1.f / (1.f + __expf(-(zhi + c3v)));
        }
    }
}

// ---------------------------------------------------------------------------
// kernel_launch
// ---------------------------------------------------------------------------
extern "C" void kernel_launch(void* const* d_in, const int* in_sizes, int n_in,
                              void* d_out, int out_size)
{
    const float* x     = (const float*)d_in[0];
    const float* u     = (const float*)d_in[1];
    const int*   batch = (const int*)d_in[2];
    const int*   hidx  = (const int*)d_in[3];
    const int*   bh    = (const int*)d_in[4];

    int N = in_sizes[0] / 6;
    int G = in_sizes[1] / 4;
    int E = in_sizes[4];

    int wb = (in_sizes[5] == 1) ? 6 : 5;   // skip scalar "r" if present
    const float* W1 = (const float*)d_in[wb + 0];
    const float* b1 = (const float*)d_in[wb + 1];
    const float* W2 = (const float*)d_in[wb + 2];
    const float* b2 = (const float*)d_in[wb + 3];
    const float* W3 = (const float*)d_in[wb + 4];
    const float* b3 = (const float*)d_in[wb + 5];
    const float* Wt = (const float*)d_in[wb + 6];
    const float* V1 = (const float*)d_in[wb + 7];
    const float* c1 = (const float*)d_in[wb + 8];
    const float* V2 = (const float*)d_in[wb + 9];
    const float* c2 = (const float*)d_in[wb + 10];
    const float* V3 = (const float*)d_in[wb + 11];
    const float* c3 = (const float*)d_in[wb + 12];

    int writeBatch = (out_size >= 2 * E) ? 1 : 0;

    k_node_mlp<<<(N + WPB - 1) / WPB, 256>>>(x, u, batch, W1, b1, W2, b2, W3, b3, N);
    k_segstats<<<G, 512>>>(hidx, bh, E);

    int nsm = 148;
    cudaDeviceGetAttribute(&nsm, cudaDevAttrMultiProcessorCount, 0);
    cudaFuncSetAttribute(k_main_mma, cudaFuncAttributeMaxDynamicSharedMemorySize, SMEM_MAIN);
    k_main_mma<<<nsm * 2, 256, SMEM_MAIN>>>(bh, Wt, V1, c1, V2, c2, V3, c3,
                                            (float*)d_out, E, writeBatch);
}

// round 5
// speedup vs baseline: 2.8898x; 1.1369x over previous
#include <cuda_runtime.h>
#include <cuda_fp16.h>
#include <cstdint>
#include <math.h>

// Problem constants (fixed shapes for this registry entry)
#define NMAX 32768
#define GMAX 2048
#define EMAX 1146880
#define WPB  8

// Scratch (no cudaMalloc allowed)
__device__ __half  g_h[NMAX * 64];         // node embeddings fp16 [N,64] (4 MB)
__device__ float2  g_segmr[GMAX * 64];     // per-graph per-feature (max, 1/sum)
__device__ __half  g_xh[(size_t)EMAX * 64];// hyperedge features, fp16 (147 MB)

// ---------------------------------------------------------------------------
// PTX wrappers (portable tensor path: ldmatrix + mma.sync, compute_103-safe)
// ---------------------------------------------------------------------------
__device__ __forceinline__ uint32_t smem_u32(const void* p) {
    uint32_t a;
    asm("{ .reg .u64 t; cvta.to.shared.u64 t, %1; cvt.u32.u64 %0, t; }" : "=r"(a) : "l"(p));
    return a;
}
__device__ __forceinline__ void ldsm4(uint32_t& r0, uint32_t& r1, uint32_t& r2, uint32_t& r3,
                                      uint32_t addr) {
    asm volatile("ldmatrix.sync.aligned.m8n8.x4.shared.b16 {%0,%1,%2,%3}, [%4];"
                 : "=r"(r0), "=r"(r1), "=r"(r2), "=r"(r3) : "r"(addr));
}
__device__ __forceinline__ void mma_f16(float d[4], uint32_t a0, uint32_t a1, uint32_t a2,
                                        uint32_t a3, uint32_t b0, uint32_t b1) {
    asm volatile(
        "mma.sync.aligned.m16n8k16.row.col.f32.f16.f16.f32 "
        "{%0,%1,%2,%3},{%4,%5,%6,%7},{%8,%9},{%0,%1,%2,%3};"
        : "+f"(d[0]), "+f"(d[1]), "+f"(d[2]), "+f"(d[3])
        : "r"(a0), "r"(a1), "r"(a2), "r"(a3), "r"(b0), "r"(b1));
}
// pack two f32 into half2 register (lo, hi)
__device__ __forceinline__ uint32_t pack_h2(float lo, float hi) {
    uint32_t r;
    asm("cvt.rn.f16x2.f32 %0, %1, %2;" : "=r"(r) : "f"(hi), "f"(lo));
    return r;
}

// ---------------------------------------------------------------------------
// K1: node MLP  h = (x || u[batch]) -> 64 -> 64 -> 64   (one warp per node)
// Output stored fp16, feature-adjacent pairs (via smem transpose of the
// lane/lane+32 register layout).
// ---------------------------------------------------------------------------
__global__ void k_node_mlp(const float* __restrict__ x, const float* __restrict__ u,
                           const int* __restrict__ batch,
                           const float* __restrict__ W1, const float* __restrict__ b1,
                           const float* __restrict__ W2, const float* __restrict__ b2,
                           const float* __restrict__ W3, const float* __restrict__ b3,
                           int n)
{
    __shared__ float sW1[10 * 64];
    __shared__ float2 sW2p[64 * 32], sW3p[64 * 32];
    __shared__ float sb1[64], sb2[64], sb3[64];
    __shared__ float sh[WPB][64];

    for (int i = threadIdx.x; i < 10 * 64; i += blockDim.x) sW1[i] = W1[i];
    for (int i = threadIdx.x; i < 64 * 32; i += blockDim.x) {
        int k = i >> 5, j = i & 31;
        sW2p[i] = make_float2(W2[k * 64 + j], W2[k * 64 + j + 32]);
        sW3p[i] = make_float2(W3[k * 64 + j], W3[k * 64 + j + 32]);
    }
    for (int i = threadIdx.x; i < 64; i += blockDim.x) { sb1[i] = b1[i]; sb2[i] = b2[i]; sb3[i] = b3[i]; }
    __syncthreads();

    int wl = threadIdx.x >> 5, lane = threadIdx.x & 31;
    int node = blockIdx.x * WPB + wl;
    if (node >= n) return;

    int bidx = __ldg(batch + node);
    float vin = 0.f;
    if (lane < 6)       vin = x[node * 6 + lane];
    else if (lane < 10) vin = u[bidx * 4 + lane - 6];

    float a0 = sb1[lane], a1 = sb1[lane + 32];
#pragma unroll
    for (int k = 0; k < 10; k++) {
        float xv = __shfl_sync(0xffffffffu, vin, k);
        a0 = fmaf(xv, sW1[k * 64 + lane], a0);
        a1 = fmaf(xv, sW1[k * 64 + lane + 32], a1);
    }
    sh[wl][lane] = fmaxf(a0, 0.f);
    sh[wl][lane + 32] = fmaxf(a1, 0.f);
    __syncwarp();

    a0 = sb2[lane]; a1 = sb2[lane + 32];
#pragma unroll 8
    for (int k = 0; k < 64; k++) {
        float xv = sh[wl][k];
        float2 wv = sW2p[k * 32 + lane];
        a0 = fmaf(xv, wv.x, a0);
        a1 = fmaf(xv, wv.y, a1);
    }
    a0 = fmaxf(a0, 0.f); a1 = fmaxf(a1, 0.f);
    __syncwarp();
    sh[wl][lane] = a0; sh[wl][lane + 32] = a1;
    __syncwarp();

    a0 = sb3[lane]; a1 = sb3[lane + 32];
#pragma unroll 8
    for (int k = 0; k < 64; k++) {
        float xv = sh[wl][k];
        float2 wv = sW3p[k * 32 + lane];
        a0 = fmaf(xv, wv.x, a0);
        a1 = fmaf(xv, wv.y, a1);
    }
    // transpose to feature-adjacent pairs, store half2
    __syncwarp();
    sh[wl][lane] = a0; sh[wl][lane + 32] = a1;
    __syncwarp();
    ((__half2*)g_h)[node * 32 + lane] =
        __floats2half2_rn(sh[wl][2 * lane], sh[wl][2 * lane + 1]);
}

// ---------------------------------------------------------------------------
// K2: segment softmax stats + materialize x_hyper as fp16.
// One block per graph; 512 threads = 16 edge slots x 32 lanes (2 feats/lane).
// ---------------------------------------------------------------------------
__device__ __forceinline__ int lbound(const int* __restrict__ a, int n, int key)
{
    int lo = 0, hi = n;
    while (lo < hi) { int mid = (lo + hi) >> 1; if (a[mid] < key) lo = mid + 1; else hi = mid; }
    return lo;
}

__global__ __launch_bounds__(512)
void k_segstats(const int* __restrict__ hidx, const int* __restrict__ bh, int E)
{
    int g = blockIdx.x;
    int lo = lbound(bh, E, g);
    int hi = lbound(bh, E, g + 1);

    int lane = threadIdx.x & 31;   // feature-pair index
    int s = threadIdx.x >> 5;      // 0..15 edge slot

    const __half2* H = (const __half2*)g_h;
    __half2* XH = (__half2*)g_xh;

    float m0 = -3.0e38f, m1 = -3.0e38f, s0 = 0.f, s1 = 0.f;
#pragma unroll 2
    for (int e = lo + s; e < hi; e += 16) {
        int i0 = __ldg(hidx + e), i1 = __ldg(hidx + E + e), i2 = __ldg(hidx + 2 * E + e);
        float2 a = __half22float2(H[i0 * 32 + lane]);
        float2 b = __half22float2(H[i1 * 32 + lane]);
        float2 c = __half22float2(H[i2 * 32 + lane]);
        float x0 = a.x + b.x + c.x;
        float x1 = a.y + b.y + c.y;
        XH[(size_t)e * 32 + lane] = __floats2half2_rn(x0, x1);
        float mn0 = fmaxf(m0, x0);
        s0 = s0 * __expf(m0 - mn0) + __expf(x0 - mn0);
        m0 = mn0;
        float mn1 = fmaxf(m1, x1);
        s1 = s1 * __expf(m1 - mn1) + __expf(x1 - mn1);
        m1 = mn1;
    }
    __shared__ float2 smx[16][32], ssm[16][32];
    smx[s][lane] = make_float2(m0, m1);
    ssm[s][lane] = make_float2(s0, s1);
    __syncthreads();
    if (threadIdx.x < 32) {
        int l = threadIdx.x;
        float M0 = -3.0e38f, M1 = -3.0e38f;
#pragma unroll
        for (int j = 0; j < 16; j++) {
            float2 mv = smx[j][l];
            M0 = fmaxf(M0, mv.x);
            M1 = fmaxf(M1, mv.y);
        }
        float S0 = 0.f, S1 = 0.f;
#pragma unroll
        for (int j = 0; j < 16; j++) {
            float2 mv = smx[j][l];
            float2 sv = ssm[j][l];
            S0 += sv.x * __expf(mv.x - M0);
            S1 += sv.y * __expf(mv.y - M1);
        }
        float R0 = (S0 > 0.f) ? (1.f / S0) : 0.f;
        float R1 = (S1 > 0.f) ? (1.f / S1) : 0.f;
        g_segmr[g * 64 + 2 * l]     = make_float2(M0, R0);
        g_segmr[g * 64 + 2 * l + 1] = make_float2(M1, R1);
    }
}

// ---------------------------------------------------------------------------
// K3: fp16 tensor-core main kernel with in-register GEMM chaining and a
// uniform-graph fast path for softmax-stat loads (batch_hyper is sorted,
// so ~97% of 16-edge tiles lie in a single graph).
//
// SMEM layout (bytes):
//   0      sWt  [64n][64k]  fp16 swz   (8192)
//   8192   sV1  [64n][128k] fp16 swz   (16384)
//   24576  sV2  [64n][64k]  fp16 swz   (8192)
//   32768  c1[64] f32 | 33024 c2[64] | 33280 V3[64] | 33536 c3
//   33792  per-warp: sxh(2048) scf(2048)  x 8 warps
// ---------------------------------------------------------------------------
#define OFF_WT  0
#define OFF_V1  8192
#define OFF_V2  24576
#define OFF_C1  32768
#define OFF_C2  33024
#define OFF_V3  33280
#define OFF_C3  33536
#define OFF_WRP 33792
#define WRP_SZ  4096
#define SMEM_MAIN (OFF_WRP + 8 * WRP_SZ)   // 66560

__global__ __launch_bounds__(256, 2)
void k_main_mma(const int* __restrict__ bh,
                const float* __restrict__ Wt,
                const float* __restrict__ V1, const float* __restrict__ c1,
                const float* __restrict__ V2, const float* __restrict__ c2,
                const float* __restrict__ V3, const float* __restrict__ c3,
                float* __restrict__ out, int E, int writeBatch)
{
    extern __shared__ __align__(128) char smem[];
    uint32_t sb = smem_u32(smem);
    int tid = threadIdx.x;

    // ---- stage weights as [n][k] fp16, xor-swizzled per row ----
    for (int i = tid; i < 64 * 64; i += 256) {
        int n = i >> 6, k = i & 63;
        uint32_t off = (uint32_t)n * 128 + (((uint32_t)k * 2) ^ (((uint32_t)n & 7) * 16));
        *(__half*)(smem + OFF_WT + off) = __float2half(Wt[k * 64 + n]);
        *(__half*)(smem + OFF_V2 + off) = __float2half(V2[k * 64 + n]);
    }
    for (int i = tid; i < 64 * 128; i += 256) {
        int n = i >> 7, k = i & 127;
        uint32_t off = (uint32_t)n * 256 + (((uint32_t)k * 2) ^ (((uint32_t)n & 7) * 16));
        *(__half*)(smem + OFF_V1 + off) = __float2half(V1[k * 64 + n]);
    }
    for (int i = tid; i < 64; i += 256) {
        ((float*)(smem + OFF_C1))[i] = c1[i];
        ((float*)(smem + OFF_C2))[i] = c2[i];
        ((float*)(smem + OFF_V3))[i] = V3[i];
    }
    if (tid == 0) *(float*)(smem + OFF_C3) = c3[0];
    __syncthreads();

    const float* sc1 = (const float*)(smem + OFF_C1);
    const float* sc2 = (const float*)(smem + OFF_C2);
    const float* sV3 = (const float*)(smem + OFF_V3);
    const float  c3v = *(const float*)(smem + OFF_C3);

    int warp = tid >> 5, lane = tid & 31;
    char* wbase = smem + OFF_WRP + warp * WRP_SZ;
    char* sxh  = wbase;          // 16 x 128B
    char* scf  = wbase + 2048;
    uint32_t sxh_u = sb + OFF_WRP + warp * WRP_SZ;

    // per-lane ldmatrix address components
    int rowA = lane & 15;
    uint32_t aOff = (uint32_t)rowA * 128;
    uint32_t aKx  = ((uint32_t)(lane >> 4)) * 16;           // k-halve select
    uint32_t aXor = ((uint32_t)(rowA & 7)) * 16;

    int rowB = (lane & 7) + ((lane >> 4) & 1) * 8;          // n within 16-tile
    uint32_t bKx  = ((uint32_t)((lane >> 3) & 1)) * 16;     // k-halve select
    uint32_t bXor = ((uint32_t)(lane & 7)) * 16;

    int qr = lane >> 2;       // 0..7 : D-frag row base
    int qc = lane & 3;        // D-frag column pair selector
    uint32_t qxor = (uint32_t)qr * 16;

    int ngrp = (E + 15) >> 4;
    int gwid = blockIdx.x * 8 + warp;
    int nwrp = gridDim.x * 8;

    for (int grp = gwid; grp < ngrp; grp += nwrp) {
        int e0 = grp << 4;
        __syncwarp();

        // ---- stage: load xh (fp16), compute softmax coef, fill sxh/scf ----
        const __half2* xin = (const __half2*)(g_xh + (size_t)e0 * 64);
        int elast = min(e0 + 15, E - 1);
        int g0 = __ldg(bh + e0);
        if (__ldg(bh + elast) == g0) {
            // fast path: whole tile in one graph — load stats once
            float4 mr = *(const float4*)(g_segmr + (size_t)g0 * 64 + 2 * lane);
#pragma unroll 4
            for (int it = 0; it < 16; it++) {
                int e = e0 + it;
                uint32_t off = (uint32_t)it * 128 + (((uint32_t)lane * 4) ^ (((uint32_t)it & 7) * 16));
                if (e < E) {
                    __half2 xh2 = xin[it * 32 + lane];
                    float2 xv = __half22float2(xh2);
                    float cfa = __expf(xv.x - mr.x) * mr.y;
                    float cfb = __expf(xv.y - mr.z) * mr.w;
                    *(__half2*)(sxh + off) = xh2;
                    *(__half2*)(scf + off) = __floats2half2_rn(cfa, cfb);
                } else {
                    *(__half2*)(sxh + off) = __floats2half2_rn(0.f, 0.f);
                    *(__half2*)(scf + off) = __floats2half2_rn(0.f, 0.f);
                }
            }
            if (writeBatch && lane < 16) {
                int e = e0 + lane;
                if (e < E) out[E + e] = (float)g0;
            }
        } else {
            // slow path: tile spans graph boundary
#pragma unroll 4
            for (int it = 0; it < 16; it++) {
                int e = e0 + it;
                uint32_t off = (uint32_t)it * 128 + (((uint32_t)lane * 4) ^ (((uint32_t)it & 7) * 16));
                if (e < E) {
                    int g = __ldg(bh + e);
                    __half2 xh2 = xin[it * 32 + lane];
                    float2 xv = __half22float2(xh2);
                    float4 mr = *(const float4*)(g_segmr + (size_t)g * 64 + 2 * lane);
                    float cfa = __expf(xv.x - mr.x) * mr.y;
                    float cfb = __expf(xv.y - mr.z) * mr.w;
                    *(__half2*)(sxh + off) = xh2;
                    *(__half2*)(scf + off) = __floats2half2_rn(cfa, cfb);
                    if (writeBatch && lane == 0) out[E + e] = (float)g;
                } else {
                    *(__half2*)(sxh + off) = __floats2half2_rn(0.f, 0.f);
                    *(__half2*)(scf + off) = __floats2half2_rn(0.f, 0.f);
                }
            }
        }
        __syncwarp();

        float d[8][4];
        uint32_t axh[4][4];    // A-frags of xh (k 0..63), reused by GEMM1+GEMM2
        uint32_t ax2[4][4];    // A-frags of xhh (GEMM2 k 64..127), then o1 (GEMM3)

        // ================= GEMM1: D = xh @ weight =================
#pragma unroll
        for (int j = 0; j < 8; j++) { d[j][0] = 0.f; d[j][1] = 0.f; d[j][2] = 0.f; d[j][3] = 0.f; }
#pragma unroll
        for (int kt = 0; kt < 4; kt++) {
            ldsm4(axh[kt][0], axh[kt][1], axh[kt][2], axh[kt][3],
                  sxh_u + aOff + (((uint32_t)kt * 32 + aKx) ^ aXor));
#pragma unroll
            for (int jt = 0; jt < 4; jt++) {
                uint32_t b0, b1, b2, b3;
                uint32_t baddr = sb + OFF_WT + (uint32_t)(jt * 16 + rowB) * 128
                               + (((uint32_t)kt * 32 + bKx) ^ bXor);
                ldsm4(b0, b1, b2, b3, baddr);
                mma_f16(d[2 * jt],     axh[kt][0], axh[kt][1], axh[kt][2], axh[kt][3], b0, b1);
                mma_f16(d[2 * jt + 1], axh[kt][0], axh[kt][1], axh[kt][2], axh[kt][3], b2, b3);
            }
        }
        // epi1 (in registers): xhh = cf * relu(D) -> A-frags for GEMM2 k 64..127
#pragma unroll
        for (int kt = 0; kt < 4; kt++) {
            int j0 = 2 * kt, j1 = j0 + 1;
            uint32_t o00 = (uint32_t)qr * 128 + (((uint32_t)(j0 * 16 + qc * 4)) ^ qxor);
            uint32_t o10 = (uint32_t)qr * 128 + (((uint32_t)(j1 * 16 + qc * 4)) ^ qxor);
            float2 cfa = __half22float2(*(__half2*)(scf + o00));
            float2 cfb = __half22float2(*(__half2*)(scf + o00 + 1024));
            float2 cfc = __half22float2(*(__half2*)(scf + o10));
            float2 cfd = __half22float2(*(__half2*)(scf + o10 + 1024));
            ax2[kt][0] = pack_h2(fmaxf(d[j0][0], 0.f) * cfa.x, fmaxf(d[j0][1], 0.f) * cfa.y);
            ax2[kt][1] = pack_h2(fmaxf(d[j0][2], 0.f) * cfb.x, fmaxf(d[j0][3], 0.f) * cfb.y);
            ax2[kt][2] = pack_h2(fmaxf(d[j1][0], 0.f) * cfc.x, fmaxf(d[j1][1], 0.f) * cfc.y);
            ax2[kt][3] = pack_h2(fmaxf(d[j1][2], 0.f) * cfd.x, fmaxf(d[j1][3], 0.f) * cfd.y);
        }

        // ================= GEMM2: D = [xh | xhh] @ V1 =================
#pragma unroll
        for (int j = 0; j < 8; j++) { d[j][0] = 0.f; d[j][1] = 0.f; d[j][2] = 0.f; d[j][3] = 0.f; }
#pragma unroll
        for (int kt = 0; kt < 8; kt++) {
            const uint32_t* a = (kt < 4) ? axh[kt] : ax2[kt - 4];
#pragma unroll
            for (int jt = 0; jt < 4; jt++) {
                uint32_t b0, b1, b2, b3;
                uint32_t baddr = sb + OFF_V1 + (uint32_t)(jt * 16 + rowB) * 256
                               + (((uint32_t)kt * 32 + bKx) ^ bXor);
                ldsm4(b0, b1, b2, b3, baddr);
                mma_f16(d[2 * jt],     a[0], a[1], a[2], a[3], b0, b1);
                mma_f16(d[2 * jt + 1], a[0], a[1], a[2], a[3], b2, b3);
            }
        }
        // epi2 (in registers): o1 = relu(D + c1) -> A-frags for GEMM3
#pragma unroll
        for (int kt = 0; kt < 4; kt++) {
            int j0 = 2 * kt, j1 = j0 + 1;
            float2 bv0 = *(const float2*)(sc1 + j0 * 8 + qc * 2);
            float2 bv1 = *(const float2*)(sc1 + j1 * 8 + qc * 2);
            ax2[kt][0] = pack_h2(fmaxf(d[j0][0] + bv0.x, 0.f), fmaxf(d[j0][1] + bv0.y, 0.f));
            ax2[kt][1] = pack_h2(fmaxf(d[j0][2] + bv0.x, 0.f), fmaxf(d[j0][3] + bv0.y, 0.f));
            ax2[kt][2] = pack_h2(fmaxf(d[j1][0] + bv1.x, 0.f), fmaxf(d[j1][1] + bv1.y, 0.f));
            ax2[kt][3] = pack_h2(fmaxf(d[j1][2] + bv1.x, 0.f), fmaxf(d[j1][3] + bv1.y, 0.f));
        }

        // ================= GEMM3: D = o1 @ V2 =================
#pragma unroll
        for (int j = 0; j < 8; j++) { d[j][0] = 0.f; d[j][1] = 0.f; d[j][2] = 0.f; d[j][3] = 0.f; }
#pragma unroll
        for (int kt = 0; kt < 4; kt++) {
#pragma unroll
            for (int jt = 0; jt < 4; jt++) {
                uint32_t b0, b1, b2, b3;
                uint32_t baddr = sb + OFF_V2 + (uint32_t)(jt * 16 + rowB) * 128
                               + (((uint32_t)kt * 32 + bKx) ^ bXor);
                ldsm4(b0, b1, b2, b3, baddr);
                mma_f16(d[2 * jt],     ax2[kt][0], ax2[kt][1], ax2[kt][2], ax2[kt][3], b0, b1);
                mma_f16(d[2 * jt + 1], ax2[kt][0], ax2[kt][1], ax2[kt][2], ax2[kt][3], b2, b3);
            }
        }
        // epi3: o2 = relu(D + c2); z = o2 . V3 + c3; out = sigmoid(z)
        float zlo = 0.f, zhi = 0.f;
#pragma unroll
        for (int j = 0; j < 8; j++) {
            int col = j * 8 + qc * 2;
            float2 bv = *(const float2*)(sc2 + col);
            float2 wv = *(const float2*)(sV3 + col);
            zlo = fmaf(fmaxf(d[j][0] + bv.x, 0.f), wv.x, zlo);
            zlo = fmaf(fmaxf(d[j][1] + bv.y, 0.f), wv.y, zlo);
            zhi = fmaf(fmaxf(d[j][2] + bv.x, 0.f), wv.x, zhi);
            zhi = fmaf(fmaxf(d[j][3] + bv.y, 0.f), wv.y, zhi);
        }
        zlo += __shfl_xor_sync(0xffffffffu, zlo, 1);
        zlo += __shfl_xor_sync(0xffffffffu, zlo, 2);
        zhi += __shfl_xor_sync(0xffffffffu, zhi, 1);
        zhi += __shfl_xor_sync(0xffffffffu, zhi, 2);
        if (qc == 0) {
            int ea = e0 + qr, eb = e0 + qr + 8;
            if (ea < E) out[ea] = 1.f / (1.f + __expf(-(zlo + c3v)));
            if (eb < E) out[eb] = 1.f / (1.f + __expf(-(zhi + c3v)));
        }
    }
}

// ---------------------------------------------------------------------------
// kernel_launch
// ---------------------------------------------------------------------------
extern "C" void kernel_launch(void* const* d_in, const int* in_sizes, int n_in,
                              void* d_out, int out_size)
{
    const float* x     = (const float*)d_in[0];
    const float* u     = (const float*)d_in[1];
    const int*   batch = (const int*)d_in[2];
    const int*   hidx  = (const int*)d_in[3];
    const int*   bh    = (const int*)d_in[4];

    int N = in_sizes[0] / 6;
    int G = in_sizes[1] / 4;
    int E = in_sizes[4];

    int wb = (in_sizes[5] == 1) ? 6 : 5;   // skip scalar "r" if present
    const float* W1 = (const float*)d_in[wb + 0];
    const float* b1 = (const float*)d_in[wb + 1];
    const float* W2 = (const float*)d_in[wb + 2];
    const float* b2 = (const float*)d_in[wb + 3];
    const float* W3 = (const float*)d_in[wb + 4];
    const float* b3 = (const float*)d_in[wb + 5];
    const float* Wt = (const float*)d_in[wb + 6];
    const float* V1 = (const float*)d_in[wb + 7];
    const float* c1 = (const float*)d_in[wb + 8];
    const float* V2 = (const float*)d_in[wb + 9];
    const float* c2 = (const float*)d_in[wb + 10];
    const float* V3 = (const float*)d_in[wb + 11];
    const float* c3 = (const float*)d_in[wb + 12];

    int writeBatch = (out_size >= 2 * E) ? 1 : 0;

    k_node_mlp<<<(N + WPB - 1) / WPB, 256>>>(x, u, batch, W1, b1, W2, b2, W3, b3, N);
    k_segstats<<<G, 512>>>(hidx, bh, E);

    int nsm = 148;
    cudaDeviceGetAttribute(&nsm, cudaDevAttrMultiProcessorCount, 0);
    cudaFuncSetAttribute(k_main_mma, cudaFuncAttributeMaxDynamicSharedMemorySize, SMEM_MAIN);
    k_main_mma<<<nsm * 2, 256, SMEM_MAIN>>>(bh, Wt, V1, c1, V2, c2, V3, c3,
                                            (float*)d_out, E, writeBatch);
}